// round 12
// baseline (speedup 1.0000x reference)
#include <cuda_runtime.h>
#include <cuda_bf16.h>
#include <math.h>
#include <stdint.h>

#define NN 100000
#define EE 3200000
#define IN_DIM 512
#define H1 64
#define H2 32
#define H3 16
#define OUTD 40
#define BN_EPS 1e-5f

// ---------------- scratch (device globals: allocation-free) ----------------
__device__ uint32_t g_sup1q[NN * 32];   // int16x2-quantized sup1 rows (64 cols -> 32 uints)
__device__ float    g_scale1[NN];       // per-row dequant scale
__device__ float g_h1  [NN * H1];
__device__ float g_sup2[NN * H2];
__device__ float g_h2  [NN * H2];
__device__ float g_sup3[NN * H3];
__device__ float g_h3  [NN * H3];
__device__ float g_h3n [NN * H3];
__device__ int   g_rowptr[NN + 1];
__device__ float g_stats[384];   // A(+0), B(+128), C(+256): sum[f], sumsq[64+f]

// ---------------- big GEMM + merged setup ----------------
// Blocks [0, gemmBlocks): C[n x 64] = A[n x 512] @ B[512 x 64], int16-quantized output.
// Blocks [gemmBlocks, ...): zero stats + build CSR rowptr (edge_row sorted).
__global__ __launch_bounds__(256) void gemm_setup_kernel(
    const float* __restrict__ A, const float* __restrict__ B,
    uint32_t* __restrict__ Cq, float* __restrict__ scale, int n,
    const int* __restrict__ erow, int e, int gemmBlocks)
{
    __shared__ __align__(16) float As[32][68];
    __shared__ __align__(16) float Bs[32][64];

    if (blockIdx.x >= gemmBlocks) {
        // ---- setup path ----
        int z = (blockIdx.x - gemmBlocks) * 256 + threadIdx.x;
        if (z < 384) g_stats[z] = 0.f;
        if (z >= e) return;
        int r = erow[z];
        int prev = (z == 0) ? -1 : erow[z - 1];
        for (int q = prev + 1; q <= r; q++) g_rowptr[q] = z;
        if (z == e - 1) {
            for (int q = r + 1; q <= n; q++) g_rowptr[q] = e;
        }
        return;
    }

    int tid = threadIdx.x;
    int tx = tid & 15;
    int ty = tid >> 4;
    int rowBase = blockIdx.x * 64;

    int ar  = tid >> 3;
    int ac4 = tid & 7;
    int bk  = tid >> 4;
    int bn4 = tid & 15;

    float acc[4][4] = {};

    for (int k0 = 0; k0 < IN_DIM; k0 += 32) {
        #pragma unroll
        for (int rr = 0; rr < 2; rr++) {
            int r = ar + rr * 32;
            int grow = rowBase + r;
            float4 v = make_float4(0.f, 0.f, 0.f, 0.f);
            if (grow < n)
                v = *reinterpret_cast<const float4*>(A + (size_t)grow * IN_DIM + k0 + ac4 * 4);
            As[ac4 * 4 + 0][r] = v.x;
            As[ac4 * 4 + 1][r] = v.y;
            As[ac4 * 4 + 2][r] = v.z;
            As[ac4 * 4 + 3][r] = v.w;
        }
        #pragma unroll
        for (int kk2 = 0; kk2 < 2; kk2++) {
            int k = bk + kk2 * 16;
            float4 v = *reinterpret_cast<const float4*>(B + (size_t)(k0 + k) * 64 + bn4 * 4);
            *reinterpret_cast<float4*>(&Bs[k][bn4 * 4]) = v;
        }
        __syncthreads();

        #pragma unroll
        for (int kk = 0; kk < 32; kk++) {
            float a[4], b[4];
            *reinterpret_cast<float4*>(a) = *reinterpret_cast<const float4*>(&As[kk][ty * 4]);
            *reinterpret_cast<float4*>(b) = *reinterpret_cast<const float4*>(&Bs[kk][tx * 4]);
            #pragma unroll
            for (int i = 0; i < 4; i++)
                #pragma unroll
                for (int j = 0; j < 4; j++)
                    acc[i][j] += a[i] * b[j];
        }
        __syncthreads();
    }

    // epilogue: per-row int16 quantization (row = 16 lanes with same ty)
    #pragma unroll
    for (int i = 0; i < 4; i++) {
        float m = fmaxf(fmaxf(fabsf(acc[i][0]), fabsf(acc[i][1])),
                        fmaxf(fabsf(acc[i][2]), fabsf(acc[i][3])));
        #pragma unroll
        for (int off = 1; off < 16; off <<= 1)
            m = fmaxf(m, __shfl_xor_sync(0xffffffffu, m, off));
        float inv = (m > 0.f) ? 32767.f / m : 0.f;
        int q0 = __float2int_rn(acc[i][0] * inv);
        int q1 = __float2int_rn(acc[i][1] * inv);
        int q2 = __float2int_rn(acc[i][2] * inv);
        int q3 = __float2int_rn(acc[i][3] * inv);
        uint32_t p0 = (q0 & 0xFFFF) | ((q1 & 0xFFFF) << 16);
        uint32_t p1 = (q2 & 0xFFFF) | ((q3 & 0xFFFF) << 16);
        int grow = rowBase + ty * 4 + i;
        if (grow < n) {
            *reinterpret_cast<uint2*>(Cq + (size_t)grow * 32 + tx * 2) = make_uint2(p0, p1);
            if (tx == 0) scale[grow] = m * (1.f / 32767.f);
        }
    }
}

// ---------------- SpMM(64) on quantized sup1, fused with BN-stats ----------------
__global__ __launch_bounds__(256) void spmm64q_stats_kernel(
    const uint32_t* __restrict__ supq, const float* __restrict__ scale,
    const int* __restrict__ col, const float* __restrict__ val,
    float* __restrict__ out, float* __restrict__ stats, int n)
{
    int wid  = threadIdx.x >> 5;
    int lane = threadIdx.x & 31;

    __shared__ float sm[8][64];
    float2* o2 = reinterpret_cast<float2*>(out);
    float sx = 0.f, sy = 0.f, qx = 0.f, qy = 0.f;
    for (int r = blockIdx.x * 8 + wid; r < n; r += gridDim.x * 8) {
        int e = g_rowptr[r], eend = g_rowptr[r + 1];
        float2 acc = make_float2(0.f, 0.f);
        #pragma unroll 4
        for (; e < eend; e++) {
            int   c = __ldg(col + e);
            float v = __ldg(val + e);
            float m = v * __ldg(scale + c);
            uint32_t w = __ldg(supq + (size_t)c * 32 + lane);
            float lo = (float)((short)(w & 0xFFFFu));
            float hi = (float)((short)(w >> 16));
            acc.x += m * lo;
            acc.y += m * hi;
        }
        o2[(size_t)r * 32 + lane] = acc;
        sx += acc.x; sy += acc.y;
        qx += acc.x * acc.x; qy += acc.y * acc.y;
    }
    sm[wid][2 * lane] = sx; sm[wid][2 * lane + 1] = sy;
    __syncthreads();
    if (threadIdx.x < 64) {
        float s = 0.f;
        #pragma unroll
        for (int w = 0; w < 8; w++) s += sm[w][threadIdx.x];
        atomicAdd(&stats[threadIdx.x], s);
    }
    __syncthreads();
    sm[wid][2 * lane] = qx; sm[wid][2 * lane + 1] = qy;
    __syncthreads();
    if (threadIdx.x < 64) {
        float s = 0.f;
        #pragma unroll
        for (int w = 0; w < 8; w++) s += sm[w][threadIdx.x];
        atomicAdd(&stats[64 + threadIdx.x], s);
    }
}

// ---------------- persistent SpMM fused with BN-stats (fp32, F=32/16) ----------------
template <int F>
__global__ __launch_bounds__(256) void spmm_stats_kernel(
    const float* __restrict__ sup, const int* __restrict__ col,
    const float* __restrict__ val, float* __restrict__ out,
    float* __restrict__ stats, int n)
{
    int wid  = threadIdx.x >> 5;
    int lane = threadIdx.x & 31;

    if constexpr (F == 32) {
        __shared__ float sm[8][32];
        float sx = 0.f, qx = 0.f;
        for (int r = blockIdx.x * 8 + wid; r < n; r += gridDim.x * 8) {
            int e = g_rowptr[r], eend = g_rowptr[r + 1];
            float acc = 0.f;
            #pragma unroll 4
            for (; e < eend; e++) {
                int   c = __ldg(col + e);
                float v = __ldg(val + e);
                acc += v * __ldg(sup + (size_t)c * 32 + lane);
            }
            out[(size_t)r * 32 + lane] = acc;
            sx += acc; qx += acc * acc;
        }
        sm[wid][lane] = sx;
        __syncthreads();
        if (threadIdx.x < 32) {
            float s = 0.f;
            #pragma unroll
            for (int w = 0; w < 8; w++) s += sm[w][threadIdx.x];
            atomicAdd(&stats[threadIdx.x], s);
        }
        __syncthreads();
        sm[wid][lane] = qx;
        __syncthreads();
        if (threadIdx.x < 32) {
            float s = 0.f;
            #pragma unroll
            for (int w = 0; w < 8; w++) s += sm[w][threadIdx.x];
            atomicAdd(&stats[64 + threadIdx.x], s);
        }
    } else {  // F == 16: two rows per warp (half-warps)
        __shared__ float sm[8][32];
        int half = lane >> 4;
        int f    = lane & 15;
        float sx = 0.f, qx = 0.f;
        for (int r = blockIdx.x * 16 + wid * 2 + half; r < n; r += gridDim.x * 16) {
            int e = g_rowptr[r], eend = g_rowptr[r + 1];
            float acc = 0.f;
            #pragma unroll 4
            for (; e < eend; e++) {
                int   c = __ldg(col + e);
                float v = __ldg(val + e);
                acc += v * __ldg(sup + (size_t)c * 16 + f);
            }
            out[(size_t)r * 16 + f] = acc;
            sx += acc; qx += acc * acc;
        }
        sm[wid][lane] = sx;
        __syncthreads();
        if (threadIdx.x < 16) {
            float s = 0.f;
            #pragma unroll
            for (int w = 0; w < 8; w++) s += sm[w][threadIdx.x] + sm[w][threadIdx.x + 16];
            atomicAdd(&stats[threadIdx.x], s);
        }
        __syncthreads();
        sm[wid][lane] = qx;
        __syncthreads();
        if (threadIdx.x < 16) {
            float s = 0.f;
            #pragma unroll
            for (int w = 0; w < 8; w++) s += sm[w][threadIdx.x] + sm[w][threadIdx.x + 16];
            atomicAdd(&stats[64 + threadIdx.x], s);
        }
    }
}

// ---------------- fused BN+ELU+GEMM, tiled: C[n x M] = elu(bn(A)) @ W ----------------
template <int K, int M>
__global__ __launch_bounds__(256) void bn_gemm_kernel(
    const float* __restrict__ A, const float* __restrict__ stats,
    const float* __restrict__ gamma, const float* __restrict__ beta,
    const float* __restrict__ W, float* __restrict__ C, int n)
{
    constexpr int BM = 128;
    constexpr int AROW = BM + 4;
    constexpr int WPAD = M + 4;
    constexpr int TC = M / 4;
    constexpr int TR = BM / (256 / TC);

    __shared__ __align__(16) float As[K][AROW];
    __shared__ __align__(16) float Ws[K][WPAD];
    __shared__ float sScale[K], sShift[K];

    int tid = threadIdx.x;
    int rowBase = blockIdx.x * BM;

    if (tid < K) {
        float invN = 1.f / (float)n;
        float mean = stats[tid] * invN;
        float var  = stats[64 + tid] * invN - mean * mean;
        float inv  = rsqrtf(var + BN_EPS);
        float sc = inv * gamma[tid];
        sScale[tid] = sc;
        sShift[tid] = beta[tid] - mean * sc;
    }
    for (int i = tid; i < K * M; i += 256)
        Ws[i / M][i % M] = W[i];
    __syncthreads();

    constexpr int NF4 = BM * (K / 4) / 256;
    #pragma unroll
    for (int u = 0; u < NF4; u++) {
        int slot = u * 256 + tid;
        int r  = slot / (K / 4);
        int c4 = slot % (K / 4);
        float4 v = make_float4(0.f, 0.f, 0.f, 0.f);
        if (rowBase + r < n)
            v = *reinterpret_cast<const float4*>(A + (size_t)(rowBase + r) * K + c4 * 4);
        int k = c4 * 4;
        float t0 = v.x * sScale[k + 0] + sShift[k + 0];
        float t1 = v.y * sScale[k + 1] + sShift[k + 1];
        float t2 = v.z * sScale[k + 2] + sShift[k + 2];
        float t3 = v.w * sScale[k + 3] + sShift[k + 3];
        As[k + 0][r] = (t0 > 0.f) ? t0 : expm1f(t0);
        As[k + 1][r] = (t1 > 0.f) ? t1 : expm1f(t1);
        As[k + 2][r] = (t2 > 0.f) ? t2 : expm1f(t2);
        As[k + 3][r] = (t3 > 0.f) ? t3 : expm1f(t3);
    }
    __syncthreads();

    int tx = tid % TC;
    int ty = tid / TC;

    float acc[TR][4];
    #pragma unroll
    for (int i = 0; i < TR; i++)
        #pragma unroll
        for (int j = 0; j < 4; j++) acc[i][j] = 0.f;

    #pragma unroll 16
    for (int k = 0; k < K; k++) {
        float b[4];
        *reinterpret_cast<float4*>(b) = *reinterpret_cast<const float4*>(&Ws[k][tx * 4]);
        float a[TR];
        if constexpr (TR == 4) {
            *reinterpret_cast<float4*>(a) = *reinterpret_cast<const float4*>(&As[k][ty * 4]);
        } else {
            *reinterpret_cast<float2*>(a) = *reinterpret_cast<const float2*>(&As[k][ty * 2]);
        }
        #pragma unroll
        for (int i = 0; i < TR; i++)
            #pragma unroll
            for (int j = 0; j < 4; j++)
                acc[i][j] += a[i] * b[j];
    }

    #pragma unroll
    for (int i = 0; i < TR; i++) {
        int row = rowBase + ty * TR + i;
        if (row < n) {
            *reinterpret_cast<float4*>(C + (size_t)row * M + tx * 4) =
                make_float4(acc[i][0], acc[i][1], acc[i][2], acc[i][3]);
        }
    }
}

// ---------------- BN+ELU elementwise on h3 (16-dim) -> h3n ----------------
__global__ __launch_bounds__(256) void bn_elu16_kernel(
    const float* __restrict__ h, const float* __restrict__ stats,
    const float* __restrict__ gamma, const float* __restrict__ beta,
    float* __restrict__ hn, int n)
{
    int idx = blockIdx.x * blockDim.x + threadIdx.x;
    if (idx >= n * H3) return;
    int f = idx & 15;
    float invN = 1.f / (float)n;
    float mean = stats[f] * invN;
    float var  = stats[64 + f] * invN - mean * mean;
    float inv  = rsqrtf(var + BN_EPS);
    float sc = inv * __ldg(gamma + f);
    float sh = __ldg(beta + f) - mean * sc;
    float v = h[idx] * sc + sh;
    hn[idx] = (v > 0.f) ? v : expm1f(v);
}

// ---------------- final: SpMM(16) -> GEMM 16x40 -> log_softmax -> d_out ----------------
__global__ __launch_bounds__(256) void spmm16_gemm40_lsm_kernel(
    const float* __restrict__ hn, const int* __restrict__ col,
    const float* __restrict__ val, const float* __restrict__ W4,
    float* __restrict__ out, int n)
{
    __shared__ float sW[H3 * OUTD];
    for (int i = threadIdx.x; i < H3 * OUTD; i += blockDim.x) sW[i] = W4[i];
    __syncthreads();

    int gw = (blockIdx.x * blockDim.x + threadIdx.x) >> 5;
    int lane = threadIdx.x & 31;
    if (gw >= n) return;

    int e0 = g_rowptr[gw], e1 = g_rowptr[gw + 1];
    int half = lane >> 4;
    int f    = lane & 15;

    float acc = 0.f;
    #pragma unroll 2
    for (int e = e0 + half; e < e1; e += 2) {
        int   c = __ldg(col + e);
        float v = __ldg(val + e);
        acc += v * __ldg(hn + (size_t)c * 16 + f);
    }
    acc += __shfl_xor_sync(0xffffffffu, acc, 16);

    bool second = (lane < 8);
    float o0 = 0.f, o1 = 0.f;
    #pragma unroll
    for (int k = 0; k < 16; k++) {
        float ak = __shfl_sync(0xffffffffu, acc, k);
        o0 += ak * sW[k * OUTD + lane];
        if (second) o1 += ak * sW[k * OUTD + 32 + lane];
    }

    float m = o0;
    if (second) m = fmaxf(m, o1);
    #pragma unroll
    for (int off = 16; off > 0; off >>= 1)
        m = fmaxf(m, __shfl_xor_sync(0xffffffffu, m, off));
    float s = __expf(o0 - m);
    if (second) s += __expf(o1 - m);
    #pragma unroll
    for (int off = 16; off > 0; off >>= 1)
        s += __shfl_xor_sync(0xffffffffu, s, off);
    float lse = m + logf(s);
    out[(size_t)gw * 40 + lane] = o0 - lse;
    if (second) out[(size_t)gw * 40 + 32 + lane] = o1 - lse;
}

// ---------------- launch ----------------
extern "C" void kernel_launch(void* const* d_in, const int* in_sizes, int n_in,
                              void* d_out, int out_size) {
    const float* x        = (const float*)d_in[0];
    const int*   edge_row = (const int*)  d_in[1];
    const int*   edge_col = (const int*)  d_in[2];
    const float* edge_val = (const float*)d_in[3];
    const float* W1 = (const float*)d_in[4];
    const float* W2 = (const float*)d_in[5];
    const float* W3 = (const float*)d_in[6];
    const float* W4 = (const float*)d_in[7];
    const float* g1 = (const float*)d_in[8];
    const float* b1 = (const float*)d_in[9];
    const float* g2 = (const float*)d_in[10];
    const float* b2 = (const float*)d_in[11];
    const float* g3 = (const float*)d_in[12];
    const float* b3 = (const float*)d_in[13];
    float* out = (float*)d_out;

    int n = in_sizes[0] / IN_DIM;   // 100000
    int e = in_sizes[1];            // 3200000

    uint32_t* sup1q; cudaGetSymbolAddress((void**)&sup1q, g_sup1q);
    float* scale1; cudaGetSymbolAddress((void**)&scale1, g_scale1);
    float* h1;   cudaGetSymbolAddress((void**)&h1,   g_h1);
    float* sup2; cudaGetSymbolAddress((void**)&sup2, g_sup2);
    float* h2;   cudaGetSymbolAddress((void**)&h2,   g_h2);
    float* sup3; cudaGetSymbolAddress((void**)&sup3, g_sup3);
    float* h3;   cudaGetSymbolAddress((void**)&h3,   g_h3);
    float* h3n;  cudaGetSymbolAddress((void**)&h3n,  g_h3n);
    float* stats; cudaGetSymbolAddress((void**)&stats, g_stats);
    float* stA = stats, *stB = stats + 128, *stC = stats + 256;

    const int SPMM_GRID = 592;  // 4 blocks/SM

    int gemmBlocks  = (n + 63) / 64;
    int setupBlocks = (e + 255) / 256;

    // 1: layer-1 GEMM (quantized epilogue) + overlapped setup (rowptr + zero stats)
    gemm_setup_kernel<<<gemmBlocks + setupBlocks, 256>>>(
        x, W1, sup1q, scale1, n, edge_row, e, gemmBlocks);
    // 2: SpMM(64) on int16 sup + stats A
    spmm64q_stats_kernel<<<SPMM_GRID, 256>>>(sup1q, scale1, edge_col, edge_val, h1, stA, n);
    // 3: bn_elu(A) + GEMM 64->32 (tiled)
    bn_gemm_kernel<64, 32><<<(n + 127) / 128, 256>>>(h1, stA, g1, b1, W2, sup2, n);
    // 4: SpMM(32) + stats B
    spmm_stats_kernel<32><<<SPMM_GRID, 256>>>(sup2, edge_col, edge_val, h2, stB, n);
    // 5: bn_elu(B) + GEMM 32->16 (tiled)
    bn_gemm_kernel<32, 16><<<(n + 127) / 128, 256>>>(h2, stB, g2, b2, W3, sup3, n);
    // 6: SpMM(16) + stats C
    spmm_stats_kernel<16><<<SPMM_GRID, 256>>>(sup3, edge_col, edge_val, h3, stC, n);
    // 7: bn_elu on h3 -> h3n
    bn_elu16_kernel<<<((size_t)n * 16 + 255) / 256, 256>>>(h3, stC, g3, b3, h3n, n);
    // 8: SpMM(16) + 16x40 GEMM + log_softmax (reordered layer 4)
    spmm16_gemm40_lsm_kernel<<<((size_t)n * 32 + 255) / 256, 256>>>(h3n, edge_col, edge_val, W4, out, n);
}

// round 13
// speedup vs baseline: 1.2391x; 1.2391x over previous
#include <cuda_runtime.h>
#include <cuda_bf16.h>
#include <math.h>
#include <stdint.h>

#define NN 100000
#define EE 3200000
#define IN_DIM 512
#define H1 64
#define H2 32
#define H3 16
#define OUTD 40
#define BN_EPS 1e-5f

// ---------------- scratch (device globals: allocation-free) ----------------
__device__ float g_sup1[NN * H1];
__device__ float g_h1  [NN * H1];
__device__ float g_sup2[NN * H2];
__device__ float g_h2  [NN * H2];
__device__ float g_sup3[NN * H3];
__device__ float g_h3  [NN * H3];
__device__ float g_h3n [NN * H3];
__device__ int   g_rowptr[NN + 1];
__device__ float g_stats[384];   // A(+0), B(+128), C(+256): sum[f], sumsq[64+f]

// ---------------- setup: zero stats + CSR rowptr (edge_row sorted) ----------------
__global__ void setup_kernel(const int* __restrict__ row, int n, int e) {
    int z = blockIdx.x * blockDim.x + threadIdx.x;
    if (z < 384) g_stats[z] = 0.f;
    int i = z;
    if (i >= e) return;
    int r = row[i];
    int prev = (i == 0) ? -1 : row[i - 1];
    for (int q = prev + 1; q <= r; q++) g_rowptr[q] = i;
    if (i == e - 1) {
        for (int q = r + 1; q <= n; q++) g_rowptr[q] = e;
    }
}

// ---------------- big GEMM: C[n x 64] = A[n x 512] @ B[512 x 64] ----------------
// BM=64, BN=64, BK=32, 256 threads, 4x4 micro-tile (fp32 FFMA roofline; proven).
__global__ __launch_bounds__(256) void gemm512x64_kernel(
    const float* __restrict__ A, const float* __restrict__ B,
    float* __restrict__ C, int n)
{
    __shared__ __align__(16) float As[32][68];
    __shared__ __align__(16) float Bs[32][64];

    int tid = threadIdx.x;
    int tx = tid & 15;
    int ty = tid >> 4;
    int rowBase = blockIdx.x * 64;

    int ar  = tid >> 3;
    int ac4 = tid & 7;
    int bk  = tid >> 4;
    int bn4 = tid & 15;

    float acc[4][4] = {};

    for (int k0 = 0; k0 < IN_DIM; k0 += 32) {
        #pragma unroll
        for (int rr = 0; rr < 2; rr++) {
            int r = ar + rr * 32;
            int grow = rowBase + r;
            float4 v = make_float4(0.f, 0.f, 0.f, 0.f);
            if (grow < n)
                v = *reinterpret_cast<const float4*>(A + (size_t)grow * IN_DIM + k0 + ac4 * 4);
            As[ac4 * 4 + 0][r] = v.x;
            As[ac4 * 4 + 1][r] = v.y;
            As[ac4 * 4 + 2][r] = v.z;
            As[ac4 * 4 + 3][r] = v.w;
        }
        #pragma unroll
        for (int kk2 = 0; kk2 < 2; kk2++) {
            int k = bk + kk2 * 16;
            float4 v = *reinterpret_cast<const float4*>(B + (size_t)(k0 + k) * 64 + bn4 * 4);
            *reinterpret_cast<float4*>(&Bs[k][bn4 * 4]) = v;
        }
        __syncthreads();

        #pragma unroll
        for (int kk = 0; kk < 32; kk++) {
            float a[4], b[4];
            *reinterpret_cast<float4*>(a) = *reinterpret_cast<const float4*>(&As[kk][ty * 4]);
            *reinterpret_cast<float4*>(b) = *reinterpret_cast<const float4*>(&Bs[kk][tx * 4]);
            #pragma unroll
            for (int i = 0; i < 4; i++)
                #pragma unroll
                for (int j = 0; j < 4; j++)
                    acc[i][j] += a[i] * b[j];
        }
        __syncthreads();
    }

    #pragma unroll
    for (int i = 0; i < 4; i++) {
        int grow = rowBase + ty * 4 + i;
        if (grow < n) {
            *reinterpret_cast<float4*>(C + (size_t)grow * 64 + tx * 4) =
                make_float4(acc[i][0], acc[i][1], acc[i][2], acc[i][3]);
        }
    }
}

// ---------------- persistent SpMM fused with BN-stats accumulation ----------------
template <int F>
__global__ __launch_bounds__(256) void spmm_stats_kernel(
    const float* __restrict__ sup, const int* __restrict__ col,
    const float* __restrict__ val, float* __restrict__ out,
    float* __restrict__ stats, int n)
{
    int wid  = threadIdx.x >> 5;
    int lane = threadIdx.x & 31;

    if constexpr (F == 64) {
        __shared__ float sm[8][64];
        const float2* s2 = reinterpret_cast<const float2*>(sup);
        float2* o2 = reinterpret_cast<float2*>(out);
        float sx = 0.f, sy = 0.f, qx = 0.f, qy = 0.f;
        for (int r = blockIdx.x * 8 + wid; r < n; r += gridDim.x * 8) {
            int e = g_rowptr[r], eend = g_rowptr[r + 1];
            float2 acc = make_float2(0.f, 0.f);
            #pragma unroll 8
            for (; e < eend; e++) {
                int   c = __ldg(col + e);
                float v = __ldg(val + e);
                float2 sv = __ldg(s2 + (size_t)c * 32 + lane);
                acc.x += v * sv.x;
                acc.y += v * sv.y;
            }
            o2[(size_t)r * 32 + lane] = acc;
            sx += acc.x; sy += acc.y;
            qx += acc.x * acc.x; qy += acc.y * acc.y;
        }
        sm[wid][2 * lane] = sx; sm[wid][2 * lane + 1] = sy;
        __syncthreads();
        if (threadIdx.x < 64) {
            float s = 0.f;
            #pragma unroll
            for (int w = 0; w < 8; w++) s += sm[w][threadIdx.x];
            atomicAdd(&stats[threadIdx.x], s);
        }
        __syncthreads();
        sm[wid][2 * lane] = qx; sm[wid][2 * lane + 1] = qy;
        __syncthreads();
        if (threadIdx.x < 64) {
            float s = 0.f;
            #pragma unroll
            for (int w = 0; w < 8; w++) s += sm[w][threadIdx.x];
            atomicAdd(&stats[64 + threadIdx.x], s);
        }
    } else if constexpr (F == 32) {
        __shared__ float sm[8][32];
        float sx = 0.f, qx = 0.f;
        for (int r = blockIdx.x * 8 + wid; r < n; r += gridDim.x * 8) {
            int e = g_rowptr[r], eend = g_rowptr[r + 1];
            float acc = 0.f;
            #pragma unroll 8
            for (; e < eend; e++) {
                int   c = __ldg(col + e);
                float v = __ldg(val + e);
                acc += v * __ldg(sup + (size_t)c * 32 + lane);
            }
            out[(size_t)r * 32 + lane] = acc;
            sx += acc; qx += acc * acc;
        }
        sm[wid][lane] = sx;
        __syncthreads();
        if (threadIdx.x < 32) {
            float s = 0.f;
            #pragma unroll
            for (int w = 0; w < 8; w++) s += sm[w][threadIdx.x];
            atomicAdd(&stats[threadIdx.x], s);
        }
        __syncthreads();
        sm[wid][lane] = qx;
        __syncthreads();
        if (threadIdx.x < 32) {
            float s = 0.f;
            #pragma unroll
            for (int w = 0; w < 8; w++) s += sm[w][threadIdx.x];
            atomicAdd(&stats[64 + threadIdx.x], s);
        }
    } else {  // F == 16: two rows per warp (half-warps)
        __shared__ float sm[8][32];
        int half = lane >> 4;
        int f    = lane & 15;
        float sx = 0.f, qx = 0.f;
        for (int r = blockIdx.x * 16 + wid * 2 + half; r < n; r += gridDim.x * 16) {
            int e = g_rowptr[r], eend = g_rowptr[r + 1];
            float acc = 0.f;
            #pragma unroll 8
            for (; e < eend; e++) {
                int   c = __ldg(col + e);
                float v = __ldg(val + e);
                acc += v * __ldg(sup + (size_t)c * 16 + f);
            }
            out[(size_t)r * 16 + f] = acc;
            sx += acc; qx += acc * acc;
        }
        sm[wid][lane] = sx;
        __syncthreads();
        if (threadIdx.x < 16) {
            float s = 0.f;
            #pragma unroll
            for (int w = 0; w < 8; w++) s += sm[w][threadIdx.x] + sm[w][threadIdx.x + 16];
            atomicAdd(&stats[threadIdx.x], s);
        }
        __syncthreads();
        sm[wid][lane] = qx;
        __syncthreads();
        if (threadIdx.x < 16) {
            float s = 0.f;
            #pragma unroll
            for (int w = 0; w < 8; w++) s += sm[w][threadIdx.x] + sm[w][threadIdx.x + 16];
            atomicAdd(&stats[64 + threadIdx.x], s);
        }
    }
}

// ---------------- fused BN+ELU+GEMM, tiled: C[n x M] = elu(bn(A)) @ W ----------------
template <int K, int M>
__global__ __launch_bounds__(256) void bn_gemm_kernel(
    const float* __restrict__ A, const float* __restrict__ stats,
    const float* __restrict__ gamma, const float* __restrict__ beta,
    const float* __restrict__ W, float* __restrict__ C, int n)
{
    constexpr int BM = 128;
    constexpr int AROW = BM + 4;
    constexpr int WPAD = M + 4;
    constexpr int TC = M / 4;
    constexpr int TR = BM / (256 / TC);

    __shared__ __align__(16) float As[K][AROW];
    __shared__ __align__(16) float Ws[K][WPAD];
    __shared__ float sScale[K], sShift[K];

    int tid = threadIdx.x;
    int rowBase = blockIdx.x * BM;

    if (tid < K) {
        float invN = 1.f / (float)n;
        float mean = stats[tid] * invN;
        float var  = stats[64 + tid] * invN - mean * mean;
        float inv  = rsqrtf(var + BN_EPS);
        float sc = inv * gamma[tid];
        sScale[tid] = sc;
        sShift[tid] = beta[tid] - mean * sc;
    }
    for (int i = tid; i < K * M; i += 256)
        Ws[i / M][i % M] = W[i];
    __syncthreads();

    constexpr int NF4 = BM * (K / 4) / 256;
    #pragma unroll
    for (int u = 0; u < NF4; u++) {
        int slot = u * 256 + tid;
        int r  = slot / (K / 4);
        int c4 = slot % (K / 4);
        float4 v = make_float4(0.f, 0.f, 0.f, 0.f);
        if (rowBase + r < n)
            v = *reinterpret_cast<const float4*>(A + (size_t)(rowBase + r) * K + c4 * 4);
        int k = c4 * 4;
        float t0 = v.x * sScale[k + 0] + sShift[k + 0];
        float t1 = v.y * sScale[k + 1] + sShift[k + 1];
        float t2 = v.z * sScale[k + 2] + sShift[k + 2];
        float t3 = v.w * sScale[k + 3] + sShift[k + 3];
        As[k + 0][r] = (t0 > 0.f) ? t0 : expm1f(t0);
        As[k + 1][r] = (t1 > 0.f) ? t1 : expm1f(t1);
        As[k + 2][r] = (t2 > 0.f) ? t2 : expm1f(t2);
        As[k + 3][r] = (t3 > 0.f) ? t3 : expm1f(t3);
    }
    __syncthreads();

    int tx = tid % TC;
    int ty = tid / TC;

    float acc[TR][4];
    #pragma unroll
    for (int i = 0; i < TR; i++)
        #pragma unroll
        for (int j = 0; j < 4; j++) acc[i][j] = 0.f;

    #pragma unroll 16
    for (int k = 0; k < K; k++) {
        float b[4];
        *reinterpret_cast<float4*>(b) = *reinterpret_cast<const float4*>(&Ws[k][tx * 4]);
        float a[TR];
        if constexpr (TR == 4) {
            *reinterpret_cast<float4*>(a) = *reinterpret_cast<const float4*>(&As[k][ty * 4]);
        } else {
            *reinterpret_cast<float2*>(a) = *reinterpret_cast<const float2*>(&As[k][ty * 2]);
        }
        #pragma unroll
        for (int i = 0; i < TR; i++)
            #pragma unroll
            for (int j = 0; j < 4; j++)
                acc[i][j] += a[i] * b[j];
    }

    #pragma unroll
    for (int i = 0; i < TR; i++) {
        int row = rowBase + ty * TR + i;
        if (row < n) {
            *reinterpret_cast<float4*>(C + (size_t)row * M + tx * 4) =
                make_float4(acc[i][0], acc[i][1], acc[i][2], acc[i][3]);
        }
    }
}

// ---------------- BN+ELU elementwise on h3 (16-dim) -> h3n ----------------
__global__ __launch_bounds__(256) void bn_elu16_kernel(
    const float* __restrict__ h, const float* __restrict__ stats,
    const float* __restrict__ gamma, const float* __restrict__ beta,
    float* __restrict__ hn, int n)
{
    int idx = blockIdx.x * blockDim.x + threadIdx.x;
    if (idx >= n * H3) return;
    int f = idx & 15;
    float invN = 1.f / (float)n;
    float mean = stats[f] * invN;
    float var  = stats[64 + f] * invN - mean * mean;
    float inv  = rsqrtf(var + BN_EPS);
    float sc = inv * __ldg(gamma + f);
    float sh = __ldg(beta + f) - mean * sc;
    float v = h[idx] * sc + sh;
    hn[idx] = (v > 0.f) ? v : expm1f(v);
}

// ---------------- final: SpMM(16) -> GEMM 16x40 -> log_softmax -> d_out ----------------
__global__ __launch_bounds__(256) void spmm16_gemm40_lsm_kernel(
    const float* __restrict__ hn, const int* __restrict__ col,
    const float* __restrict__ val, const float* __restrict__ W4,
    float* __restrict__ out, int n)
{
    __shared__ float sW[H3 * OUTD];
    for (int i = threadIdx.x; i < H3 * OUTD; i += blockDim.x) sW[i] = W4[i];
    __syncthreads();

    int gw = (blockIdx.x * blockDim.x + threadIdx.x) >> 5;
    int lane = threadIdx.x & 31;
    if (gw >= n) return;

    int e0 = g_rowptr[gw], e1 = g_rowptr[gw + 1];
    int half = lane >> 4;
    int f    = lane & 15;

    float acc = 0.f;
    #pragma unroll 4
    for (int e = e0 + half; e < e1; e += 2) {
        int   c = __ldg(col + e);
        float v = __ldg(val + e);
        acc += v * __ldg(hn + (size_t)c * 16 + f);
    }
    acc += __shfl_xor_sync(0xffffffffu, acc, 16);

    bool second = (lane < 8);
    float o0 = 0.f, o1 = 0.f;
    #pragma unroll
    for (int k = 0; k < 16; k++) {
        float ak = __shfl_sync(0xffffffffu, acc, k);
        o0 += ak * sW[k * OUTD + lane];
        if (second) o1 += ak * sW[k * OUTD + 32 + lane];
    }

    float m = o0;
    if (second) m = fmaxf(m, o1);
    #pragma unroll
    for (int off = 16; off > 0; off >>= 1)
        m = fmaxf(m, __shfl_xor_sync(0xffffffffu, m, off));
    float s = __expf(o0 - m);
    if (second) s += __expf(o1 - m);
    #pragma unroll
    for (int off = 16; off > 0; off >>= 1)
        s += __shfl_xor_sync(0xffffffffu, s, off);
    float lse = m + logf(s);
    out[(size_t)gw * 40 + lane] = o0 - lse;
    if (second) out[(size_t)gw * 40 + 32 + lane] = o1 - lse;
}

// ---------------- launch ----------------
extern "C" void kernel_launch(void* const* d_in, const int* in_sizes, int n_in,
                              void* d_out, int out_size) {
    const float* x        = (const float*)d_in[0];
    const int*   edge_row = (const int*)  d_in[1];
    const int*   edge_col = (const int*)  d_in[2];
    const float* edge_val = (const float*)d_in[3];
    const float* W1 = (const float*)d_in[4];
    const float* W2 = (const float*)d_in[5];
    const float* W3 = (const float*)d_in[6];
    const float* W4 = (const float*)d_in[7];
    const float* g1 = (const float*)d_in[8];
    const float* b1 = (const float*)d_in[9];
    const float* g2 = (const float*)d_in[10];
    const float* b2 = (const float*)d_in[11];
    const float* g3 = (const float*)d_in[12];
    const float* b3 = (const float*)d_in[13];
    float* out = (float*)d_out;

    int n = in_sizes[0] / IN_DIM;   // 100000
    int e = in_sizes[1];            // 3200000

    float* sup1; cudaGetSymbolAddress((void**)&sup1, g_sup1);
    float* h1;   cudaGetSymbolAddress((void**)&h1,   g_h1);
    float* sup2; cudaGetSymbolAddress((void**)&sup2, g_sup2);
    float* h2;   cudaGetSymbolAddress((void**)&h2,   g_h2);
    float* sup3; cudaGetSymbolAddress((void**)&sup3, g_sup3);
    float* h3;   cudaGetSymbolAddress((void**)&h3,   g_h3);
    float* h3n;  cudaGetSymbolAddress((void**)&h3n,  g_h3n);
    float* stats; cudaGetSymbolAddress((void**)&stats, g_stats);
    float* stA = stats, *stB = stats + 128, *stC = stats + 256;

    const int SPMM_GRID = 1184;  // 8 blocks/SM -> 64 warps/SM = full occupancy (was 592 = 50%)

    // 1: rowptr + zero stats
    setup_kernel<<<(e + 255) / 256, 256>>>(edge_row, n, e);
    // 2: layer-1 dense GEMM (scalar FFMA roofline)
    gemm512x64_kernel<<<(n + 63) / 64, 256>>>(x, W1, sup1, n);
    // 3: SpMM(64) + stats A
    spmm_stats_kernel<64><<<SPMM_GRID, 256>>>(sup1, edge_col, edge_val, h1, stA, n);
    // 4: bn_elu(A) + GEMM 64->32 (tiled)
    bn_gemm_kernel<64, 32><<<(n + 127) / 128, 256>>>(h1, stA, g1, b1, W2, sup2, n);
    // 5: SpMM(32) + stats B
    spmm_stats_kernel<32><<<SPMM_GRID, 256>>>(sup2, edge_col, edge_val, h2, stB, n);
    // 6: bn_elu(B) + GEMM 32->16 (tiled)
    bn_gemm_kernel<32, 16><<<(n + 127) / 128, 256>>>(h2, stB, g2, b2, W3, sup3, n);
    // 7: SpMM(16) + stats C
    spmm_stats_kernel<16><<<SPMM_GRID, 256>>>(sup3, edge_col, edge_val, h3, stC, n);
    // 8: bn_elu on h3 -> h3n
    bn_elu16_kernel<<<((size_t)n * 16 + 255) / 256, 256>>>(h3, stC, g3, b3, h3n, n);
    // 9: SpMM(16) + 16x40 GEMM + log_softmax (reordered layer 4)
    spmm16_gemm40_lsm_kernel<<<((size_t)n * 32 + 255) / 256, 256>>>(h3n, edge_col, edge_val, W4, out, n);
}

// round 14
// speedup vs baseline: 1.3588x; 1.0966x over previous
#include <cuda_runtime.h>
#include <cuda_bf16.h>
#include <math.h>
#include <stdint.h>

#define NN 100000
#define EE 3200000
#define IN_DIM 512
#define H1 64
#define H2 32
#define H3 16
#define OUTD 40
#define BN_EPS 1e-5f

// ---------------- scratch (device globals: allocation-free) ----------------
__device__ float g_sup1[NN * H1];
__device__ float g_h1  [NN * H1];
__device__ float g_sup2[NN * H2];
__device__ float g_h2  [NN * H2];
__device__ float g_sup3[NN * H3];
__device__ float g_h3  [NN * H3];
__device__ float g_h3n [NN * H3];
__device__ int   g_rowptr[NN + 1];
__device__ float g_stats[384];   // A(+0), B(+128), C(+256): sum[f], sumsq[64+f]

// ---------------- f32x2 helpers ----------------
__device__ __forceinline__ unsigned long long pack2_dup(float v) {
    unsigned long long r;
    asm("mov.b64 %0, {%1, %1};" : "=l"(r) : "f"(v));
    return r;
}
__device__ __forceinline__ unsigned long long fma2(unsigned long long a,
                                                   unsigned long long b,
                                                   unsigned long long c) {
    unsigned long long d;
    asm("fma.rn.f32x2 %0, %1, %2, %3;" : "=l"(d) : "l"(a), "l"(b), "l"(c));
    return d;
}

// ---------------- big GEMM (f32x2, broadcast-A) + merged setup ----------------
// Blocks [0, gemmBlocks): C[n x 64] = A[n x 512] @ W[512 x 64].
//   Tile 128x64, 256 threads, micro 8(M)x4(N). A transposed in smem (broadcast reads),
//   B pairs read directly as u64, A dup'd in registers. fp32 throughout.
// Blocks [gemmBlocks, ...): zero stats + CSR rowptr build (edge_row sorted).
#define GM 128
#define GN 64
#define GK 16

__global__ __launch_bounds__(256) void gemm_f2_setup_kernel(
    const float* __restrict__ A, const float* __restrict__ B,
    float* __restrict__ C, int n,
    const int* __restrict__ erow, int e, int gemmBlocks)
{
    if (blockIdx.x >= gemmBlocks) {
        int z = (blockIdx.x - gemmBlocks) * 256 + threadIdx.x;
        if (z < 384) g_stats[z] = 0.f;
        if (z >= e) return;
        int r = erow[z];
        int prev = (z == 0) ? -1 : erow[z - 1];
        for (int q = prev + 1; q <= r; q++) g_rowptr[q] = z;
        if (z == e - 1) {
            for (int q = r + 1; q <= n; q++) g_rowptr[q] = e;
        }
        return;
    }

    __shared__ __align__(16) float As[GK][GM + 4];   // [k][row], 132-stride
    __shared__ __align__(16) float Bs[GK][GN + 4];   // [k][col], 68-stride

    int tid = threadIdx.x;
    int tx = tid & 15;        // N group: cols tx*4..tx*4+3
    int ty = tid >> 4;        // M group: rows ty*8..ty*8+7
    int rowBase = blockIdx.x * GM;

    unsigned long long acc[8][2];
    #pragma unroll
    for (int i = 0; i < 8; i++) { acc[i][0] = 0ULL; acc[i][1] = 0ULL; }

    int lr  = tid >> 2;       // A-load row pair base: 2 slots per thread
    int lc4 = tid & 3;        // A-load float4 idx along k
    int bkr = tid >> 4;       // B-load k row
    int bc4 = tid & 15;       // B-load float4 col

    for (int k0 = 0; k0 < IN_DIM; k0 += GK) {
        // ---- A tile: 128 rows x 16 k, transposed ----
        #pragma unroll
        for (int u = 0; u < 2; u++) {
            int r = lr + u * 64;
            float4 v = make_float4(0.f, 0.f, 0.f, 0.f);
            if (rowBase + r < n)
                v = *reinterpret_cast<const float4*>(A + (size_t)(rowBase + r) * IN_DIM + k0 + lc4 * 4);
            As[lc4 * 4 + 0][r] = v.x;
            As[lc4 * 4 + 1][r] = v.y;
            As[lc4 * 4 + 2][r] = v.z;
            As[lc4 * 4 + 3][r] = v.w;
        }
        // ---- B tile: 16 k x 64 ----
        {
            float4 v = *reinterpret_cast<const float4*>(B + (size_t)(k0 + bkr) * GN + bc4 * 4);
            *reinterpret_cast<float4*>(&Bs[bkr][bc4 * 4]) = v;
        }
        __syncthreads();

        #pragma unroll
        for (int kk = 0; kk < GK; kk++) {
            float a[8];
            *reinterpret_cast<float4*>(a)     = *reinterpret_cast<const float4*>(&As[kk][ty * 8]);
            *reinterpret_cast<float4*>(a + 4) = *reinterpret_cast<const float4*>(&As[kk][ty * 8 + 4]);
            ulonglong2 b = *reinterpret_cast<const ulonglong2*>(&Bs[kk][tx * 4]);  // (b0,b1),(b2,b3)
            #pragma unroll
            for (int i = 0; i < 8; i++) {
                unsigned long long ad = pack2_dup(a[i]);
                acc[i][0] = fma2(ad, b.x, acc[i][0]);
                acc[i][1] = fma2(ad, b.y, acc[i][1]);
            }
        }
        __syncthreads();
    }

    #pragma unroll
    for (int i = 0; i < 8; i++) {
        int row = rowBase + ty * 8 + i;
        if (row < n) {
            ulonglong2 st; st.x = acc[i][0]; st.y = acc[i][1];
            *reinterpret_cast<ulonglong2*>(C + (size_t)row * GN + tx * 4) = st;
        }
    }
}

// ---------------- persistent SpMM fused with BN-stats accumulation ----------------
template <int F>
__global__ __launch_bounds__(256) void spmm_stats_kernel(
    const float* __restrict__ sup, const int* __restrict__ col,
    const float* __restrict__ val, float* __restrict__ out,
    float* __restrict__ stats, int n)
{
    int wid  = threadIdx.x >> 5;
    int lane = threadIdx.x & 31;

    if constexpr (F == 64) {
        __shared__ float sm[8][64];
        const float2* s2 = reinterpret_cast<const float2*>(sup);
        float2* o2 = reinterpret_cast<float2*>(out);
        float sx = 0.f, sy = 0.f, qx = 0.f, qy = 0.f;
        for (int r = blockIdx.x * 8 + wid; r < n; r += gridDim.x * 8) {
            int e = g_rowptr[r], eend = g_rowptr[r + 1];
            float2 acc = make_float2(0.f, 0.f);
            #pragma unroll 8
            for (; e < eend; e++) {
                int   c = __ldg(col + e);
                float v = __ldg(val + e);
                float2 sv = __ldg(s2 + (size_t)c * 32 + lane);
                acc.x += v * sv.x;
                acc.y += v * sv.y;
            }
            o2[(size_t)r * 32 + lane] = acc;
            sx += acc.x; sy += acc.y;
            qx += acc.x * acc.x; qy += acc.y * acc.y;
        }
        sm[wid][2 * lane] = sx; sm[wid][2 * lane + 1] = sy;
        __syncthreads();
        if (threadIdx.x < 64) {
            float s = 0.f;
            #pragma unroll
            for (int w = 0; w < 8; w++) s += sm[w][threadIdx.x];
            atomicAdd(&stats[threadIdx.x], s);
        }
        __syncthreads();
        sm[wid][2 * lane] = qx; sm[wid][2 * lane + 1] = qy;
        __syncthreads();
        if (threadIdx.x < 64) {
            float s = 0.f;
            #pragma unroll
            for (int w = 0; w < 8; w++) s += sm[w][threadIdx.x];
            atomicAdd(&stats[64 + threadIdx.x], s);
        }
    } else if constexpr (F == 32) {
        __shared__ float sm[8][32];
        float sx = 0.f, qx = 0.f;
        for (int r = blockIdx.x * 8 + wid; r < n; r += gridDim.x * 8) {
            int e = g_rowptr[r], eend = g_rowptr[r + 1];
            float acc = 0.f;
            #pragma unroll 8
            for (; e < eend; e++) {
                int   c = __ldg(col + e);
                float v = __ldg(val + e);
                acc += v * __ldg(sup + (size_t)c * 32 + lane);
            }
            out[(size_t)r * 32 + lane] = acc;
            sx += acc; qx += acc * acc;
        }
        sm[wid][lane] = sx;
        __syncthreads();
        if (threadIdx.x < 32) {
            float s = 0.f;
            #pragma unroll
            for (int w = 0; w < 8; w++) s += sm[w][threadIdx.x];
            atomicAdd(&stats[threadIdx.x], s);
        }
        __syncthreads();
        sm[wid][lane] = qx;
        __syncthreads();
        if (threadIdx.x < 32) {
            float s = 0.f;
            #pragma unroll
            for (int w = 0; w < 8; w++) s += sm[w][threadIdx.x];
            atomicAdd(&stats[64 + threadIdx.x], s);
        }
    } else {  // F == 16: two rows per warp (half-warps)
        __shared__ float sm[8][32];
        int half = lane >> 4;
        int f    = lane & 15;
        float sx = 0.f, qx = 0.f;
        for (int r = blockIdx.x * 16 + wid * 2 + half; r < n; r += gridDim.x * 16) {
            int e = g_rowptr[r], eend = g_rowptr[r + 1];
            float acc = 0.f;
            #pragma unroll 8
            for (; e < eend; e++) {
                int   c = __ldg(col + e);
                float v = __ldg(val + e);
                acc += v * __ldg(sup + (size_t)c * 16 + f);
            }
            out[(size_t)r * 16 + f] = acc;
            sx += acc; qx += acc * acc;
        }
        sm[wid][lane] = sx;
        __syncthreads();
        if (threadIdx.x < 16) {
            float s = 0.f;
            #pragma unroll
            for (int w = 0; w < 8; w++) s += sm[w][threadIdx.x] + sm[w][threadIdx.x + 16];
            atomicAdd(&stats[threadIdx.x], s);
        }
        __syncthreads();
        sm[wid][lane] = qx;
        __syncthreads();
        if (threadIdx.x < 16) {
            float s = 0.f;
            #pragma unroll
            for (int w = 0; w < 8; w++) s += sm[w][threadIdx.x] + sm[w][threadIdx.x + 16];
            atomicAdd(&stats[64 + threadIdx.x], s);
        }
    }
}

// ---------------- fused BN+ELU+GEMM, tiled: C[n x M] = elu(bn(A)) @ W ----------------
template <int K, int M>
__global__ __launch_bounds__(256) void bn_gemm_kernel(
    const float* __restrict__ A, const float* __restrict__ stats,
    const float* __restrict__ gamma, const float* __restrict__ beta,
    const float* __restrict__ W, float* __restrict__ C, int n)
{
    constexpr int BM = 128;
    constexpr int AROW = BM + 4;
    constexpr int WPAD = M + 4;
    constexpr int TC = M / 4;
    constexpr int TR = BM / (256 / TC);

    __shared__ __align__(16) float As[K][AROW];
    __shared__ __align__(16) float Ws[K][WPAD];
    __shared__ float sScale[K], sShift[K];

    int tid = threadIdx.x;
    int rowBase = blockIdx.x * BM;

    if (tid < K) {
        float invN = 1.f / (float)n;
        float mean = stats[tid] * invN;
        float var  = stats[64 + tid] * invN - mean * mean;
        float inv  = rsqrtf(var + BN_EPS);
        float sc = inv * gamma[tid];
        sScale[tid] = sc;
        sShift[tid] = beta[tid] - mean * sc;
    }
    for (int i = tid; i < K * M; i += 256)
        Ws[i / M][i % M] = W[i];
    __syncthreads();

    constexpr int NF4 = BM * (K / 4) / 256;
    #pragma unroll
    for (int u = 0; u < NF4; u++) {
        int slot = u * 256 + tid;
        int r  = slot / (K / 4);
        int c4 = slot % (K / 4);
        float4 v = make_float4(0.f, 0.f, 0.f, 0.f);
        if (rowBase + r < n)
            v = *reinterpret_cast<const float4*>(A + (size_t)(rowBase + r) * K + c4 * 4);
        int k = c4 * 4;
        float t0 = v.x * sScale[k + 0] + sShift[k + 0];
        float t1 = v.y * sScale[k + 1] + sShift[k + 1];
        float t2 = v.z * sScale[k + 2] + sShift[k + 2];
        float t3 = v.w * sScale[k + 3] + sShift[k + 3];
        As[k + 0][r] = (t0 > 0.f) ? t0 : expm1f(t0);
        As[k + 1][r] = (t1 > 0.f) ? t1 : expm1f(t1);
        As[k + 2][r] = (t2 > 0.f) ? t2 : expm1f(t2);
        As[k + 3][r] = (t3 > 0.f) ? t3 : expm1f(t3);
    }
    __syncthreads();

    int tx = tid % TC;
    int ty = tid / TC;

    float acc[TR][4];
    #pragma unroll
    for (int i = 0; i < TR; i++)
        #pragma unroll
        for (int j = 0; j < 4; j++) acc[i][j] = 0.f;

    #pragma unroll 16
    for (int k = 0; k < K; k++) {
        float b[4];
        *reinterpret_cast<float4*>(b) = *reinterpret_cast<const float4*>(&Ws[k][tx * 4]);
        float a[TR];
        if constexpr (TR == 4) {
            *reinterpret_cast<float4*>(a) = *reinterpret_cast<const float4*>(&As[k][ty * 4]);
        } else {
            *reinterpret_cast<float2*>(a) = *reinterpret_cast<const float2*>(&As[k][ty * 2]);
        }
        #pragma unroll
        for (int i = 0; i < TR; i++)
            #pragma unroll
            for (int j = 0; j < 4; j++)
                acc[i][j] += a[i] * b[j];
    }

    #pragma unroll
    for (int i = 0; i < TR; i++) {
        int row = rowBase + ty * TR + i;
        if (row < n) {
            *reinterpret_cast<float4*>(C + (size_t)row * M + tx * 4) =
                make_float4(acc[i][0], acc[i][1], acc[i][2], acc[i][3]);
        }
    }
}

// ---------------- BN+ELU elementwise on h3 (16-dim) -> h3n ----------------
__global__ __launch_bounds__(256) void bn_elu16_kernel(
    const float* __restrict__ h, const float* __restrict__ stats,
    const float* __restrict__ gamma, const float* __restrict__ beta,
    float* __restrict__ hn, int n)
{
    int idx = blockIdx.x * blockDim.x + threadIdx.x;
    if (idx >= n * H3) return;
    int f = idx & 15;
    float invN = 1.f / (float)n;
    float mean = stats[f] * invN;
    float var  = stats[64 + f] * invN - mean * mean;
    float inv  = rsqrtf(var + BN_EPS);
    float sc = inv * __ldg(gamma + f);
    float sh = __ldg(beta + f) - mean * sc;
    float v = h[idx] * sc + sh;
    hn[idx] = (v > 0.f) ? v : expm1f(v);
}

// ---------------- final: SpMM(16) -> GEMM 16x40 -> log_softmax -> d_out ----------------
__global__ __launch_bounds__(256) void spmm16_gemm40_lsm_kernel(
    const float* __restrict__ hn, const int* __restrict__ col,
    const float* __restrict__ val, const float* __restrict__ W4,
    float* __restrict__ out, int n)
{
    __shared__ float sW[H3 * OUTD];
    for (int i = threadIdx.x; i < H3 * OUTD; i += blockDim.x) sW[i] = W4[i];
    __syncthreads();

    int gw = (blockIdx.x * blockDim.x + threadIdx.x) >> 5;
    int lane = threadIdx.x & 31;
    if (gw >= n) return;

    int e0 = g_rowptr[gw], e1 = g_rowptr[gw + 1];
    int half = lane >> 4;
    int f    = lane & 15;

    float acc = 0.f;
    #pragma unroll 4
    for (int e = e0 + half; e < e1; e += 2) {
        int   c = __ldg(col + e);
        float v = __ldg(val + e);
        acc += v * __ldg(hn + (size_t)c * 16 + f);
    }
    acc += __shfl_xor_sync(0xffffffffu, acc, 16);

    bool second = (lane < 8);
    float o0 = 0.f, o1 = 0.f;
    #pragma unroll
    for (int k = 0; k < 16; k++) {
        float ak = __shfl_sync(0xffffffffu, acc, k);
        o0 += ak * sW[k * OUTD + lane];
        if (second) o1 += ak * sW[k * OUTD + 32 + lane];
    }

    float m = o0;
    if (second) m = fmaxf(m, o1);
    #pragma unroll
    for (int off = 16; off > 0; off >>= 1)
        m = fmaxf(m, __shfl_xor_sync(0xffffffffu, m, off));
    float s = __expf(o0 - m);
    if (second) s += __expf(o1 - m);
    #pragma unroll
    for (int off = 16; off > 0; off >>= 1)
        s += __shfl_xor_sync(0xffffffffu, s, off);
    float lse = m + logf(s);
    out[(size_t)gw * 40 + lane] = o0 - lse;
    if (second) out[(size_t)gw * 40 + 32 + lane] = o1 - lse;
}

// ---------------- launch ----------------
extern "C" void kernel_launch(void* const* d_in, const int* in_sizes, int n_in,
                              void* d_out, int out_size) {
    const float* x        = (const float*)d_in[0];
    const int*   edge_row = (const int*)  d_in[1];
    const int*   edge_col = (const int*)  d_in[2];
    const float* edge_val = (const float*)d_in[3];
    const float* W1 = (const float*)d_in[4];
    const float* W2 = (const float*)d_in[5];
    const float* W3 = (const float*)d_in[6];
    const float* W4 = (const float*)d_in[7];
    const float* g1 = (const float*)d_in[8];
    const float* b1 = (const float*)d_in[9];
    const float* g2 = (const float*)d_in[10];
    const float* b2 = (const float*)d_in[11];
    const float* g3 = (const float*)d_in[12];
    const float* b3 = (const float*)d_in[13];
    float* out = (float*)d_out;

    int n = in_sizes[0] / IN_DIM;   // 100000
    int e = in_sizes[1];            // 3200000

    float* sup1; cudaGetSymbolAddress((void**)&sup1, g_sup1);
    float* h1;   cudaGetSymbolAddress((void**)&h1,   g_h1);
    float* sup2; cudaGetSymbolAddress((void**)&sup2, g_sup2);
    float* h2;   cudaGetSymbolAddress((void**)&h2,   g_h2);
    float* sup3; cudaGetSymbolAddress((void**)&sup3, g_sup3);
    float* h3;   cudaGetSymbolAddress((void**)&h3,   g_h3);
    float* h3n;  cudaGetSymbolAddress((void**)&h3n,  g_h3n);
    float* stats; cudaGetSymbolAddress((void**)&stats, g_stats);
    float* stA = stats, *stB = stats + 128, *stC = stats + 256;

    const int SPMM_GRID = 1184;  // 8 blocks/SM -> full occupancy

    int gemmBlocks  = (n + GM - 1) / GM;          // 782
    int setupBlocks = (e + 255) / 256;

    // 1: layer-1 GEMM (f32x2) + overlapped setup (rowptr + zero stats)
    gemm_f2_setup_kernel<<<gemmBlocks + setupBlocks, 256>>>(
        x, W1, sup1, n, edge_row, e, gemmBlocks);
    // 2: SpMM(64) + stats A
    spmm_stats_kernel<64><<<SPMM_GRID, 256>>>(sup1, edge_col, edge_val, h1, stA, n);
    // 3: bn_elu(A) + GEMM 64->32 (tiled)
    bn_gemm_kernel<64, 32><<<(n + 127) / 128, 256>>>(h1, stA, g1, b1, W2, sup2, n);
    // 4: SpMM(32) + stats B
    spmm_stats_kernel<32><<<SPMM_GRID, 256>>>(sup2, edge_col, edge_val, h2, stB, n);
    // 5: bn_elu(B) + GEMM 32->16 (tiled)
    bn_gemm_kernel<32, 16><<<(n + 127) / 128, 256>>>(h2, stB, g2, b2, W3, sup3, n);
    // 6: SpMM(16) + stats C
    spmm_stats_kernel<16><<<SPMM_GRID, 256>>>(sup3, edge_col, edge_val, h3, stC, n);
    // 7: bn_elu on h3 -> h3n
    bn_elu16_kernel<<<((size_t)n * 16 + 255) / 256, 256>>>(h3, stC, g3, b3, h3n, n);
    // 8: SpMM(16) + 16x40 GEMM + log_softmax (reordered layer 4)
    spmm16_gemm40_lsm_kernel<<<((size_t)n * 32 + 255) / 256, 256>>>(h3n, edge_col, edge_val, W4, out, n);
}